// round 14
// baseline (speedup 1.0000x reference)
#include <cuda_runtime.h>
#include <cuda_fp16.h>
#include <math.h>
#include <stddef.h>
#include <stdint.h>

#define SEQ    2048
#define DIMM   2048
#define HEADS  16
#define DHEAD  128
#define QKVN   2304
#define K2DIM  1024          // K/2 half2 units per row
#define EPSF   1e-5f
#define MASKVF 1e-10f
#define SCALEF 0.08838834764831845f

// ---------------- scratch (hi/lo interleaved as uint2 {h,l}) -----------------
__device__ uint2    g_xn2[SEQ * K2DIM];
__device__ uint2    g_wc2[QKVN * K2DIM];     // [wq|wk|wv]^T (q pre-scaled)
__device__ uint2    g_wo2[DIMM * K2DIM];
__device__ uint2    g_ao2[SEQ * K2DIM];
__device__ uint4    g_qh4[HEADS * 128 * 8 * 32];   // Q fragments hi
__device__ uint4    g_ql4[HEADS * 128 * 8 * 32];   // Q fragments lo
__device__ uint2    g_kt2[64 * SEQ];         // K^T half2-packed along d, {h,l}
__device__ float    g_v[SEQ * DHEAD];        // V dense fp32
__device__ uint2    g_vt2[(SEQ / 2) * DHEAD];
__device__ float    g_vsuf[SEQ * DHEAD];
__device__ float    g_vpart[16 * DHEAD];

// ---------------- helpers ----------------------------------------------------
__device__ __forceinline__ void cvt_h2(float x0, float x1, unsigned& h, unsigned& l) {
    __half2 hh = __floats2half2_rn(x0, x1);
    __half2 ll = __floats2half2_rn(x0 - __low2float(hh), x1 - __high2float(hh));
    h = *reinterpret_cast<unsigned*>(&hh);
    l = *reinterpret_cast<unsigned*>(&ll);
}
__device__ __forceinline__ unsigned cvt_h(float x0, float x1) {
    __half2 hh = __floats2half2_rn(x0, x1);
    return *reinterpret_cast<unsigned*>(&hh);
}
__device__ __forceinline__ uint32_t smem_u32(const void* p) {
    uint32_t a;
    asm("{ .reg .u64 t; cvta.to.shared.u64 t, %1; cvt.u32.u64 %0, t; }"
        : "=r"(a) : "l"(p));
    return a;
}
__device__ __forceinline__ void cp_async8(uint32_t s, const void* g) {
    asm volatile("cp.async.ca.shared.global [%0], [%1], 8;" :: "r"(s), "l"(g));
}
#define CP_COMMIT() asm volatile("cp.async.commit_group;" ::: "memory")
#define CP_WAIT0()  asm volatile("cp.async.wait_group 0;" ::: "memory")
#define MMA_F16(Cacc, Av, Bv)                                               \
    asm volatile("mma.sync.aligned.m16n8k16.row.col.f32.f16.f16.f32 "       \
        "{%0,%1,%2,%3}, {%4,%5,%6,%7}, {%8,%9}, {%0,%1,%2,%3};"             \
        : "+f"((Cacc)[0]), "+f"((Cacc)[1]), "+f"((Cacc)[2]), "+f"((Cacc)[3])\
        : "r"((Av).x), "r"((Av).y), "r"((Av).z), "r"((Av).w),               \
          "r"((Bv).x), "r"((Bv).y))

// ---------------- RMSNorm -> interleaved half2 hi/lo --------------------------
__global__ void rmsnorm_split_kernel(const float* __restrict__ x,
                                     const float* __restrict__ gamma) {
    int row = blockIdx.x;
    const float* xr = x + (size_t)row * DIMM;
    float ss = 0.f;
    for (int i = threadIdx.x; i < DIMM; i += 256) { float v = xr[i]; ss += v * v; }
    __shared__ float red[8];
    #pragma unroll
    for (int o = 16; o; o >>= 1) ss += __shfl_xor_sync(0xffffffffu, ss, o);
    if ((threadIdx.x & 31) == 0) red[threadIdx.x >> 5] = ss;
    __syncthreads();
    if (threadIdx.x < 32) {
        float v = (threadIdx.x < 8) ? red[threadIdx.x] : 0.f;
        #pragma unroll
        for (int o = 4; o; o >>= 1) v += __shfl_xor_sync(0xffffffffu, v, o);
        if (threadIdx.x == 0) red[0] = v;
    }
    __syncthreads();
    float inv = rsqrtf(red[0] / (float)DIMM + EPSF);
    for (int u = threadIdx.x; u < K2DIM; u += 256) {
        float2 xv = *(const float2*)(xr + 2 * u);
        float2 gv = *(const float2*)(gamma + 2 * u);
        unsigned h, l;
        cvt_h2(xv.x * inv * gv.x, xv.y * inv * gv.y, h, l);
        g_xn2[(size_t)row * K2DIM + u] = make_uint2(h, l);
    }
}

// ---------------- fused transpose + split for all 4 weights -------------------
__global__ void transpose_split_all_kernel(const float* __restrict__ wq,
                                           const float* __restrict__ wk,
                                           const float* __restrict__ wv,
                                           const float* __restrict__ wo,
                                           uint2* __restrict__ wc2,
                                           uint2* __restrict__ wo2) {
    __shared__ float tile[32][33];
    int b = blockIdx.x;
    const float* src; uint2* dst; int C; float scale; int bx, by;
    if (b < 4096)      { src = wq; dst = wc2;                       C = DIMM;  scale = SCALEF;
                         bx = (b & 63) * 32;        by = (b >> 6) * 32; }
    else if (b < 4352) { int t = b - 4096; src = wk; dst = wc2 + (size_t)2048 * K2DIM; C = DHEAD; scale = 1.f;
                         bx = (t & 3) * 32;         by = (t >> 2) * 32; }
    else if (b < 4608) { int t = b - 4352; src = wv; dst = wc2 + (size_t)2176 * K2DIM; C = DHEAD; scale = 1.f;
                         bx = (t & 3) * 32;         by = (t >> 2) * 32; }
    else               { int t = b - 4608; src = wo; dst = wo2;     C = DIMM;  scale = 1.f;
                         bx = (t & 63) * 32;        by = (t >> 6) * 32; }

    int tx = threadIdx.x, ty = threadIdx.y;           // 32 x 8
    #pragma unroll
    for (int j = 0; j < 32; j += 8)
        tile[ty + j][tx] = src[(size_t)(by + ty + j) * C + bx + tx];
    __syncthreads();
    int ul = tx & 15, nb = ty * 2 + (tx >> 4);
    #pragma unroll
    for (int rep = 0; rep < 2; rep++) {
        int nl = nb + rep * 16;
        float v0 = tile[2 * ul][nl] * scale;
        float v1 = tile[2 * ul + 1][nl] * scale;
        unsigned h, l;
        cvt_h2(v0, v1, h, l);
        dst[(size_t)(bx + nl) * K2DIM + (by >> 1) + ul] = make_uint2(h, l);
    }
}

// ---------------- fp16 split GEMM ---------------------------------------------
// TERMS: 3 = ah*bh + ah*bl + al*bh; 1 = ah*bh.  In EPI=1, bx==17 (V tile)
// runs 1-term regardless (V only needs fp16-level precision).
template <int EPI, int TERMS>
__global__ __launch_bounds__(256) void gemm_h2_kernel(
    const uint2* __restrict__ A2, const uint2* __restrict__ B2,
    float* __restrict__ C, int N)
{
    extern __shared__ unsigned smu[];
    const int tid = threadIdx.x, lane = tid & 31, warp = tid >> 5;
    const int m0 = blockIdx.y << 7, n0 = blockIdx.x << 7;
    const int wm = warp >> 1, wn = warp & 1;
    const int gid = lane >> 2, tig = lane & 3;
    const bool lo_on = (TERMS == 3) && !(EPI == 1 && blockIdx.x == 17);

    float acc[2][8][4];
    #pragma unroll
    for (int mf = 0; mf < 2; mf++)
        #pragma unroll
        for (int nf = 0; nf < 8; nf++)
            #pragma unroll
            for (int q = 0; q < 4; q++) acc[mf][nf][q] = 0.f;

    uint2 ra2[2][4], rb2[4][2];
    const int arow = m0 + warp * 16 + gid;

    #pragma unroll
    for (int i = 0; i < 2; i++) {
        int u0 = 8 * i + tig;
        ra2[i][0] = A2[(size_t)arow * K2DIM + u0];
        ra2[i][1] = A2[(size_t)(arow + 8) * K2DIM + u0];
        ra2[i][2] = A2[(size_t)arow * K2DIM + u0 + 4];
        ra2[i][3] = A2[(size_t)(arow + 8) * K2DIM + u0 + 4];
    }
    #pragma unroll
    for (int j = 0; j < 4; j++) {
        int n = n0 + (warp + 8 * (j & 1)) * 8 + gid;
        int u0 = (j >> 1) * 8 + tig;
        rb2[j][0] = B2[(size_t)n * K2DIM + u0];
        rb2[j][1] = B2[(size_t)n * K2DIM + u0 + 4];
    }

    const int S = 64;
    for (int s = 0; s < S; s++) {
        unsigned* buf = smu + (s & 1) * 8192;
        uint4* Ah4 = (uint4*)buf;
        uint4* Al4 = (uint4*)(buf + 2048);
        uint2* Bh2 = (uint2*)(buf + 4096);
        uint2* Bl2 = (uint2*)(buf + 6144);

        #pragma unroll
        for (int i = 0; i < 2; i++) {
            int slot = warp + 8 * i;
            Ah4[slot * 32 + lane] = make_uint4(ra2[i][0].x, ra2[i][1].x, ra2[i][2].x, ra2[i][3].x);
            if (lo_on)
                Al4[slot * 32 + lane] = make_uint4(ra2[i][0].y, ra2[i][1].y, ra2[i][2].y, ra2[i][3].y);
        }
        #pragma unroll
        for (int j = 0; j < 4; j++) {
            int slot = (j >> 1) * 16 + warp + 8 * (j & 1);
            Bh2[slot * 32 + lane] = make_uint2(rb2[j][0].x, rb2[j][1].x);
            if (lo_on)
                Bl2[slot * 32 + lane] = make_uint2(rb2[j][0].y, rb2[j][1].y);
        }
        __syncthreads();

        if (s + 1 < S) {
            const int ub = (s + 1) << 4;
            #pragma unroll
            for (int i = 0; i < 2; i++) {
                int u0 = ub + 8 * i + tig;
                ra2[i][0] = A2[(size_t)arow * K2DIM + u0];
                ra2[i][1] = A2[(size_t)(arow + 8) * K2DIM + u0];
                ra2[i][2] = A2[(size_t)arow * K2DIM + u0 + 4];
                ra2[i][3] = A2[(size_t)(arow + 8) * K2DIM + u0 + 4];
            }
            #pragma unroll
            for (int j = 0; j < 4; j++) {
                int n = n0 + (warp + 8 * (j & 1)) * 8 + gid;
                int u0 = ub + (j >> 1) * 8 + tig;
                rb2[j][0] = B2[(size_t)n * K2DIM + u0];
                rb2[j][1] = B2[(size_t)n * K2DIM + u0 + 4];
            }
        }

        #pragma unroll
        for (int kk = 0; kk < 2; kk++) {
            uint4 ah[2], al[2];
            uint2 bh[8], bl[8];
            #pragma unroll
            for (int mf = 0; mf < 2; mf++) {
                int slot = kk * 8 + wm * 2 + mf;
                ah[mf] = Ah4[slot * 32 + lane];
                if (lo_on) al[mf] = Al4[slot * 32 + lane];
            }
            #pragma unroll
            for (int nf = 0; nf < 8; nf++) {
                int slot = kk * 16 + wn * 8 + nf;
                bh[nf] = Bh2[slot * 32 + lane];
                if (lo_on) bl[nf] = Bl2[slot * 32 + lane];
            }
            #pragma unroll
            for (int nf = 0; nf < 8; nf++)
                #pragma unroll
                for (int mf = 0; mf < 2; mf++)
                    MMA_F16(acc[mf][nf], ah[mf], bh[nf]);
            if (lo_on) {
                #pragma unroll
                for (int nf = 0; nf < 8; nf++)
                    #pragma unroll
                    for (int mf = 0; mf < 2; mf++)
                        MMA_F16(acc[mf][nf], ah[mf], bl[nf]);
                #pragma unroll
                for (int nf = 0; nf < 8; nf++)
                    #pragma unroll
                    for (int mf = 0; mf < 2; mf++)
                        MMA_F16(acc[mf][nf], al[mf], bh[nf]);
            }
        }
        __syncthreads();
    }

    if (EPI == 0) {
        #pragma unroll
        for (int mf = 0; mf < 2; mf++) {
            const int r0 = m0 + wm * 32 + mf * 16 + gid;
            #pragma unroll
            for (int nf = 0; nf < 8; nf++) {
                const int c = n0 + wn * 64 + nf * 8 + tig * 2;
                *(float2*)(C + (size_t)r0 * N + c) = make_float2(acc[mf][nf][0], acc[mf][nf][1]);
                *(float2*)(C + (size_t)(r0 + 8) * N + c) = make_float2(acc[mf][nf][2], acc[mf][nf][3]);
            }
        }
    } else {
        const int bx = blockIdx.x;
        if (bx < 16) {
            const int h = bx;
            #pragma unroll
            for (int mf = 0; mf < 2; mf++) {
                int rg = (m0 >> 4) + wm * 2 + mf;
                #pragma unroll
                for (int k2 = 0; k2 < 4; k2++) {
                    int kkg = wn * 4 + k2;
                    const float* e = acc[mf][2 * k2];
                    const float* o = acc[mf][2 * k2 + 1];
                    uint4 hv, lv;
                    cvt_h2(e[0], e[1], hv.x, lv.x);
                    cvt_h2(e[2], e[3], hv.y, lv.y);
                    cvt_h2(o[0], o[1], hv.z, lv.z);
                    cvt_h2(o[2], o[3], hv.w, lv.w);
                    size_t idx = ((size_t)(h * 128 + rg) * 8 + kkg) * 32 + lane;
                    g_qh4[idx] = hv;
                    g_ql4[idx] = lv;
                }
            }
        } else if (bx == 16) {
            #pragma unroll
            for (int mf = 0; mf < 2; mf++) {
                int j = m0 + wm * 32 + mf * 16 + gid;
                #pragma unroll
                for (int nf = 0; nf < 8; nf++) {
                    int d2 = wn * 32 + nf * 4 + tig;
                    unsigned h0, l0, h1, l1;
                    cvt_h2(acc[mf][nf][0], acc[mf][nf][1], h0, l0);
                    cvt_h2(acc[mf][nf][2], acc[mf][nf][3], h1, l1);
                    g_kt2[d2 * SEQ + j]     = make_uint2(h0, l0);
                    g_kt2[d2 * SEQ + j + 8] = make_uint2(h1, l1);
                }
            }
        } else {
            #pragma unroll
            for (int mf = 0; mf < 2; mf++) {
                int j = m0 + wm * 32 + mf * 16 + gid;
                #pragma unroll
                for (int nf = 0; nf < 8; nf++) {
                    int d = wn * 64 + nf * 8 + tig * 2;
                    *(float2*)&g_v[(size_t)j * DHEAD + d] =
                        make_float2(acc[mf][nf][0], acc[mf][nf][1]);
                    *(float2*)&g_v[(size_t)(j + 8) * DHEAD + d] =
                        make_float2(acc[mf][nf][2], acc[mf][nf][3]);
                }
            }
        }
    }
}

// ---------------- V j-paired interleaved half2 planes --------------------------
__global__ void vprep_kernel() {
    int t = blockIdx.x * 256 + threadIdx.x;     // 131072
    int d = t & 127, j2 = t >> 7;
    float v0 = g_v[(size_t)(2 * j2) * DHEAD + d];
    float v1 = g_v[(size_t)(2 * j2 + 1) * DHEAD + d];
    unsigned h, l;
    cvt_h2(v0, v1, h, l);
    g_vt2[j2 * DHEAD + d] = make_uint2(h, l);
}

// ---------------- V suffix sums ------------------------------------------------
__global__ void vpart_kernel() {
    int blk = blockIdx.x, d = threadIdx.x;
    float s = 0.f;
    #pragma unroll 8
    for (int r = 0; r < 128; r++)
        s += g_v[(size_t)(blk * 128 + r) * DHEAD + d];
    g_vpart[blk * DHEAD + d] = s;
}
__global__ void vsuf_kernel() {
    int blk = blockIdx.x, d = threadIdx.x;
    float acc = 0.f;
    for (int b = blk + 1; b < 16; b++) acc += g_vpart[b * DHEAD + d];
    #pragma unroll 4
    for (int r = 127; r >= 0; r--) {
        int row = blk * 128 + r;
        g_vsuf[(size_t)row * DHEAD + d] = acc;
        acc += g_v[(size_t)row * DHEAD + d];
    }
}

// ---------------- attention K/V tile prefetch (cp.async) ------------------------
__device__ __forceinline__ void attn_prefetch(uint32_t bufb, int j0,
                                              int tid, int jl, int cb) {
    #pragma unroll
    for (int it = 0; it < 16; it++) {
        int d2 = cb * 16 + it;
        cp_async8(bufb + (unsigned)(d2 * 68 + jl) * 8, &g_kt2[d2 * SEQ + j0 + jl]);
    }
    #pragma unroll
    for (int it = 0; it < 16; it++) {
        int idx = it * 256 + tid;
        int j2 = idx >> 7, d = idx & 127;
        cp_async8(bufb + (unsigned)(4352 + j2 * 132 + d) * 8,
                  &g_vt2[(j0 / 2 + j2) * DHEAD + d]);
    }
    CP_COMMIT();
}

// ---------------- row-owning fp16 tensor-core flash attention -------------------
// QK x3; PV 1-term; cp.async double-buffered K/V tiles (one sync per block).
// smem: 2 buffers x 8576 uint2 (Kint[64][68] + Vint[32][132]) = 137216 B.
__global__ __launch_bounds__(256, 1) void attn_mma_kernel(const float* __restrict__ pos_bias) {
    extern __shared__ float sm[];
    const uint32_t smb = smem_u32(sm);

    const int h  = blockIdx.y;
    const int ib = gridDim.x - 1 - blockIdx.x;
    const int i0 = ib * 128;
    const int tid = threadIdx.x, lane = tid & 31, warp = tid >> 5;
    const int gid = lane >> 2, tig = lane & 3;

    const int rg = (i0 >> 4) + warp;
    const size_t qbase = ((size_t)(h * 128 + rg) * 8) * 32 + lane;

    const int jl = tid & 63, cb = tid >> 6;
    const int r0g = i0 + warp * 16 + gid, r1g = r0g + 8;
    const int jd = 2 * ib + (warp >> 2);
    const int jbmax = 2 * ib + 1;

    float o[16][4];
    #pragma unroll
    for (int nf = 0; nf < 16; nf++)
        #pragma unroll
        for (int q = 0; q < 4; q++) o[nf][q] = 0.f;
    float m0 = -1e30f, m1 = -1e30f, l0 = 0.f, l1 = 0.f;

    attn_prefetch(smb, 0, tid, jl, cb);
    CP_WAIT0();
    __syncthreads();

    for (int jb = 0; jb <= jbmax; jb++) {
        if (jb + 1 <= jbmax)
            attn_prefetch(smb + (unsigned)(((jb + 1) & 1) * 8576) * 8,
                          (jb + 1) * 64, tid, jl, cb);

        if (jb <= jd) {
            const int j0 = jb * 64;
            const uint2* Kint = (const uint2*)sm + (jb & 1) * 8576;
            const uint2* Vint = Kint + 4352;

            float s[8][4];
            #pragma unroll
            for (int nf = 0; nf < 8; nf++)
                #pragma unroll
                for (int q = 0; q < 4; q++) s[nf][q] = 0.f;

            #pragma unroll
            for (int kk = 0; kk < 8; kk++) {
                uint4 qh = g_qh4[qbase + kk * 32];
                uint4 ql = g_ql4[qbase + kk * 32];
                const int kr0 = (kk * 8 + tig) * 68, kr1 = kr0 + 4 * 68;
                uint2 bh[8], bl[8];
                #pragma unroll
                for (int nf = 0; nf < 8; nf++) {
                    int col = nf * 8 + gid;
                    uint2 kv0 = Kint[kr0 + col];
                    uint2 kv1 = Kint[kr1 + col];
                    bh[nf] = make_uint2(kv0.x, kv1.x);
                    bl[nf] = make_uint2(kv0.y, kv1.y);
                }
                #pragma unroll
                for (int nf = 0; nf < 8; nf++) MMA_F16(s[nf], qh, bh[nf]);
                #pragma unroll
                for (int nf = 0; nf < 8; nf++) MMA_F16(s[nf], qh, bl[nf]);
                #pragma unroll
                for (int nf = 0; nf < 8; nf++) MMA_F16(s[nf], ql, bh[nf]);
            }

            const float* pb0 = pos_bias + ((size_t)h * SEQ + r0g) * SEQ + j0 + tig * 2;
            const float* pb1 = pb0 + (size_t)8 * SEQ;
            #pragma unroll
            for (int nf = 0; nf < 8; nf++) {
                float2 b0 = *(const float2*)(pb0 + nf * 8);
                float2 b1 = *(const float2*)(pb1 + nf * 8);
                s[nf][0] += b0.x; s[nf][1] += b0.y;
                s[nf][2] += b1.x; s[nf][3] += b1.y;
            }
            if (jb == jd) {
                #pragma unroll
                for (int nf = 0; nf < 8; nf++) {
                    int c = j0 + nf * 8 + tig * 2;
                    if (c > r0g)     s[nf][0] = -1e30f;
                    if (c + 1 > r0g) s[nf][1] = -1e30f;
                    if (c > r1g)     s[nf][2] = -1e30f;
                    if (c + 1 > r1g) s[nf][3] = -1e30f;
                }
            }

            float rm0 = -1e30f, rm1 = -1e30f;
            #pragma unroll
            for (int nf = 0; nf < 8; nf++) {
                rm0 = fmaxf(rm0, fmaxf(s[nf][0], s[nf][1]));
                rm1 = fmaxf(rm1, fmaxf(s[nf][2], s[nf][3]));
            }
            rm0 = fmaxf(rm0, __shfl_xor_sync(0xffffffffu, rm0, 1));
            rm0 = fmaxf(rm0, __shfl_xor_sync(0xffffffffu, rm0, 2));
            rm1 = fmaxf(rm1, __shfl_xor_sync(0xffffffffu, rm1, 1));
            rm1 = fmaxf(rm1, __shfl_xor_sync(0xffffffffu, rm1, 2));
            float mn0 = fmaxf(m0, rm0), mn1 = fmaxf(m1, rm1);
            float sc0 = __expf(m0 - mn0), sc1 = __expf(m1 - mn1);

            float rs0 = 0.f, rs1 = 0.f;
            uint4 pah[4];
            #pragma unroll
            for (int c = 0; c < 4; c++) {
                float p00 = __expf(s[2*c][0] - mn0);
                float p01 = __expf(s[2*c][1] - mn0);
                float p02 = __expf(s[2*c][2] - mn1);
                float p03 = __expf(s[2*c][3] - mn1);
                float p10 = __expf(s[2*c+1][0] - mn0);
                float p11 = __expf(s[2*c+1][1] - mn0);
                float p12 = __expf(s[2*c+1][2] - mn1);
                float p13 = __expf(s[2*c+1][3] - mn1);
                rs0 += p00 + p01 + p10 + p11;
                rs1 += p02 + p03 + p12 + p13;
                pah[c].x = cvt_h(p00, p01);
                pah[c].y = cvt_h(p02, p03);
                pah[c].z = cvt_h(p10, p11);
                pah[c].w = cvt_h(p12, p13);
            }
            rs0 += __shfl_xor_sync(0xffffffffu, rs0, 1);
            rs0 += __shfl_xor_sync(0xffffffffu, rs0, 2);
            rs1 += __shfl_xor_sync(0xffffffffu, rs1, 1);
            rs1 += __shfl_xor_sync(0xffffffffu, rs1, 2);
            l0 = l0 * sc0 + rs0;
            l1 = l1 * sc1 + rs1;
            m0 = mn0; m1 = mn1;

            #pragma unroll
            for (int nf = 0; nf < 16; nf++) {
                o[nf][0] *= sc0; o[nf][1] *= sc0;
                o[nf][2] *= sc1; o[nf][3] *= sc1;
            }
            #pragma unroll
            for (int c = 0; c < 4; c++) {
                const int vr0 = (c * 8 + tig) * 132, vr1 = vr0 + 4 * 132;
                #pragma unroll
                for (int nf = 0; nf < 16; nf++) {
                    int dcol = nf * 8 + gid;
                    uint2 bh = make_uint2(Vint[vr0 + dcol].x, Vint[vr1 + dcol].x);
                    MMA_F16(o[nf], pah[c], bh);
                }
            }
        }

        CP_WAIT0();
        __syncthreads();
    }

    float cnt0 = (float)(SEQ - 1 - r0g), cnt1 = (float)(SEQ - 1 - r1g);
    float mf0 = fmaxf(m0, MASKVF), mf1 = fmaxf(m1, MASKVF);
    float wu0 = __expf(m0 - mf0),  wu1 = __expf(m1 - mf1);
    float wk0 = __expf(MASKVF - mf0), wk1 = __expf(MASKVF - mf1);
    float iZ0 = 1.f / (l0 * wu0 + cnt0 * wk0);
    float iZ1 = 1.f / (l1 * wu1 + cnt1 * wk1);
    #pragma unroll
    for (int nf = 0; nf < 16; nf++) {
        int dcol = nf * 8 + tig * 2;
        float2 vs0 = *(const float2*)&g_vsuf[(size_t)r0g * DHEAD + dcol];
        float2 vs1 = *(const float2*)&g_vsuf[(size_t)r1g * DHEAD + dcol];
        float o00 = (o[nf][0] * wu0 + wk0 * vs0.x) * iZ0;
        float o01 = (o[nf][1] * wu0 + wk0 * vs0.y) * iZ0;
        float o10 = (o[nf][2] * wu1 + wk1 * vs1.x) * iZ1;
        float o11 = (o[nf][3] * wu1 + wk1 * vs1.y) * iZ1;
        unsigned hw, lw;
        size_t u = (size_t)(h * DHEAD + dcol) >> 1;
        cvt_h2(o00, o01, hw, lw);
        g_ao2[(size_t)r0g * K2DIM + u] = make_uint2(hw, lw);
        cvt_h2(o10, o11, hw, lw);
        g_ao2[(size_t)r1g * K2DIM + u] = make_uint2(hw, lw);
    }
}

// ---------------- launch ---------------------------------------------------------
extern "C" void kernel_launch(void* const* d_in, const int* in_sizes, int n_in,
                              void* d_out, int out_size) {
    (void)in_sizes; (void)n_in; (void)out_size;
    const float* x        = (const float*)d_in[0];
    const float* pos_bias = (const float*)d_in[1];
    const float* gamma    = (const float*)d_in[2];
    const float* wq       = (const float*)d_in[3];
    const float* wk       = (const float*)d_in[4];
    const float* wv       = (const float*)d_in[5];
    const float* wo       = (const float*)d_in[6];
    float* out = (float*)d_out;

    uint2 *xn2_p, *wc2_p, *wo2_p, *ao2_p;
    cudaGetSymbolAddress((void**)&xn2_p, g_xn2);
    cudaGetSymbolAddress((void**)&wc2_p, g_wc2);
    cudaGetSymbolAddress((void**)&wo2_p, g_wo2);
    cudaGetSymbolAddress((void**)&ao2_p, g_ao2);

    const int GEMM_SMEM = 2 * 8192 * 4;      // 65536
    const int ATTN_SMEM = 2 * 8576 * 8;      // 137216 (double-buffered tiles)
    cudaFuncSetAttribute((const void*)gemm_h2_kernel<0, 1>, cudaFuncAttributeMaxDynamicSharedMemorySize, GEMM_SMEM);
    cudaFuncSetAttribute((const void*)gemm_h2_kernel<1, 3>, cudaFuncAttributeMaxDynamicSharedMemorySize, GEMM_SMEM);
    cudaFuncSetAttribute((const void*)attn_mma_kernel, cudaFuncAttributeMaxDynamicSharedMemorySize, ATTN_SMEM);

    dim3 tb(32, 8);
    transpose_split_all_kernel<<<8704, tb>>>(wq, wk, wv, wo, wc2_p, wo2_p);

    rmsnorm_split_kernel<<<SEQ, 256>>>(x, gamma);

    gemm_h2_kernel<1, 3><<<dim3(18, 16), 256, GEMM_SMEM>>>(xn2_p, wc2_p, nullptr, QKVN);

    vprep_kernel<<<512, 256>>>();
    vpart_kernel<<<16, 128>>>();
    vsuf_kernel<<<16, 128>>>();

    attn_mma_kernel<<<dim3(16, HEADS), 256, ATTN_SMEM>>>(pos_bias);

    gemm_h2_kernel<0, 1><<<dim3(16, 16), 256, GEMM_SMEM>>>(ao2_p, wo2_p, out, DIMM);
}

// round 15
// speedup vs baseline: 1.0090x; 1.0090x over previous
#include <cuda_runtime.h>
#include <cuda_fp16.h>
#include <math.h>
#include <stddef.h>
#include <stdint.h>

#define SEQ    2048
#define DIMM   2048
#define HEADS  16
#define DHEAD  128
#define QKVN   2304
#define K2DIM  1024          // K/2 half2 units per row
#define EPSF   1e-5f
#define MASKVF 1e-10f
#define SCALEF 0.08838834764831845f

// ---------------- scratch (hi/lo interleaved as uint2 {h,l}) -----------------
__device__ uint2    g_xn2[SEQ * K2DIM];
__device__ uint2    g_wc2[QKVN * K2DIM];     // [wq|wk|wv]^T (q pre-scaled)
__device__ uint2    g_wo2[DIMM * K2DIM];
__device__ uint2    g_ao2[SEQ * K2DIM];
__device__ uint4    g_qh4[HEADS * 128 * 8 * 32];   // Q fragments hi
__device__ uint4    g_ql4[HEADS * 128 * 8 * 32];   // Q fragments lo
__device__ uint2    g_kt2[64 * SEQ];         // K^T half2-packed along d, {h,l}
__device__ float    g_v[SEQ * DHEAD];        // V dense fp32
__device__ uint2    g_vt2[(SEQ / 2) * DHEAD];
__device__ float    g_vsuf[SEQ * DHEAD];
__device__ float    g_vpart[16 * DHEAD];

// ---------------- helpers ----------------------------------------------------
__device__ __forceinline__ void cvt_h2(float x0, float x1, unsigned& h, unsigned& l) {
    __half2 hh = __floats2half2_rn(x0, x1);
    __half2 ll = __floats2half2_rn(x0 - __low2float(hh), x1 - __high2float(hh));
    h = *reinterpret_cast<unsigned*>(&hh);
    l = *reinterpret_cast<unsigned*>(&ll);
}
__device__ __forceinline__ unsigned cvt_h(float x0, float x1) {
    __half2 hh = __floats2half2_rn(x0, x1);
    return *reinterpret_cast<unsigned*>(&hh);
}
#define MMA_F16(Cacc, Av, Bv)                                               \
    asm volatile("mma.sync.aligned.m16n8k16.row.col.f32.f16.f16.f32 "       \
        "{%0,%1,%2,%3}, {%4,%5,%6,%7}, {%8,%9}, {%0,%1,%2,%3};"             \
        : "+f"((Cacc)[0]), "+f"((Cacc)[1]), "+f"((Cacc)[2]), "+f"((Cacc)[3])\
        : "r"((Av).x), "r"((Av).y), "r"((Av).z), "r"((Av).w),               \
          "r"((Bv).x), "r"((Bv).y))

// ---------------- RMSNorm -> interleaved half2 hi/lo --------------------------
__global__ void rmsnorm_split_kernel(const float* __restrict__ x,
                                     const float* __restrict__ gamma) {
    int row = blockIdx.x;
    const float* xr = x + (size_t)row * DIMM;
    float ss = 0.f;
    for (int i = threadIdx.x; i < DIMM; i += 256) { float v = xr[i]; ss += v * v; }
    __shared__ float red[8];
    #pragma unroll
    for (int o = 16; o; o >>= 1) ss += __shfl_xor_sync(0xffffffffu, ss, o);
    if ((threadIdx.x & 31) == 0) red[threadIdx.x >> 5] = ss;
    __syncthreads();
    if (threadIdx.x < 32) {
        float v = (threadIdx.x < 8) ? red[threadIdx.x] : 0.f;
        #pragma unroll
        for (int o = 4; o; o >>= 1) v += __shfl_xor_sync(0xffffffffu, v, o);
        if (threadIdx.x == 0) red[0] = v;
    }
    __syncthreads();
    float inv = rsqrtf(red[0] / (float)DIMM + EPSF);
    for (int u = threadIdx.x; u < K2DIM; u += 256) {
        float2 xv = *(const float2*)(xr + 2 * u);
        float2 gv = *(const float2*)(gamma + 2 * u);
        unsigned h, l;
        cvt_h2(xv.x * inv * gv.x, xv.y * inv * gv.y, h, l);
        g_xn2[(size_t)row * K2DIM + u] = make_uint2(h, l);
    }
}

// ---------------- fused transpose + split for all 4 weights -------------------
__global__ void transpose_split_all_kernel(const float* __restrict__ wq,
                                           const float* __restrict__ wk,
                                           const float* __restrict__ wv,
                                           const float* __restrict__ wo,
                                           uint2* __restrict__ wc2,
                                           uint2* __restrict__ wo2) {
    __shared__ float tile[32][33];
    int b = blockIdx.x;
    const float* src; uint2* dst; int C; float scale; int bx, by;
    if (b < 4096)      { src = wq; dst = wc2;                       C = DIMM;  scale = SCALEF;
                         bx = (b & 63) * 32;        by = (b >> 6) * 32; }
    else if (b < 4352) { int t = b - 4096; src = wk; dst = wc2 + (size_t)2048 * K2DIM; C = DHEAD; scale = 1.f;
                         bx = (t & 3) * 32;         by = (t >> 2) * 32; }
    else if (b < 4608) { int t = b - 4352; src = wv; dst = wc2 + (size_t)2176 * K2DIM; C = DHEAD; scale = 1.f;
                         bx = (t & 3) * 32;         by = (t >> 2) * 32; }
    else               { int t = b - 4608; src = wo; dst = wo2;     C = DIMM;  scale = 1.f;
                         bx = (t & 63) * 32;        by = (t >> 6) * 32; }

    int tx = threadIdx.x, ty = threadIdx.y;           // 32 x 8
    #pragma unroll
    for (int j = 0; j < 32; j += 8)
        tile[ty + j][tx] = src[(size_t)(by + ty + j) * C + bx + tx];
    __syncthreads();
    int ul = tx & 15, nb = ty * 2 + (tx >> 4);
    #pragma unroll
    for (int rep = 0; rep < 2; rep++) {
        int nl = nb + rep * 16;
        float v0 = tile[2 * ul][nl] * scale;
        float v1 = tile[2 * ul + 1][nl] * scale;
        unsigned h, l;
        cvt_h2(v0, v1, h, l);
        dst[(size_t)(bx + nl) * K2DIM + (by >> 1) + ul] = make_uint2(h, l);
    }
}

// ---------------- fp16 split GEMM ---------------------------------------------
// TERMS: 3 = ah*bh + ah*bl + al*bh; 1 = ah*bh.  In EPI=1, bx==17 (V tile)
// runs 1-term regardless (V only needs fp16-level precision).
template <int EPI, int TERMS>
__global__ __launch_bounds__(256) void gemm_h2_kernel(
    const uint2* __restrict__ A2, const uint2* __restrict__ B2,
    float* __restrict__ C, int N)
{
    extern __shared__ unsigned smu[];
    const int tid = threadIdx.x, lane = tid & 31, warp = tid >> 5;
    const int m0 = blockIdx.y << 7, n0 = blockIdx.x << 7;
    const int wm = warp >> 1, wn = warp & 1;
    const int gid = lane >> 2, tig = lane & 3;
    const bool lo_on = (TERMS == 3) && !(EPI == 1 && blockIdx.x == 17);

    float acc[2][8][4];
    #pragma unroll
    for (int mf = 0; mf < 2; mf++)
        #pragma unroll
        for (int nf = 0; nf < 8; nf++)
            #pragma unroll
            for (int q = 0; q < 4; q++) acc[mf][nf][q] = 0.f;

    uint2 ra2[2][4], rb2[4][2];
    const int arow = m0 + warp * 16 + gid;

    #pragma unroll
    for (int i = 0; i < 2; i++) {
        int u0 = 8 * i + tig;
        ra2[i][0] = A2[(size_t)arow * K2DIM + u0];
        ra2[i][1] = A2[(size_t)(arow + 8) * K2DIM + u0];
        ra2[i][2] = A2[(size_t)arow * K2DIM + u0 + 4];
        ra2[i][3] = A2[(size_t)(arow + 8) * K2DIM + u0 + 4];
    }
    #pragma unroll
    for (int j = 0; j < 4; j++) {
        int n = n0 + (warp + 8 * (j & 1)) * 8 + gid;
        int u0 = (j >> 1) * 8 + tig;
        rb2[j][0] = B2[(size_t)n * K2DIM + u0];
        rb2[j][1] = B2[(size_t)n * K2DIM + u0 + 4];
    }

    const int S = 64;
    for (int s = 0; s < S; s++) {
        unsigned* buf = smu + (s & 1) * 8192;
        uint4* Ah4 = (uint4*)buf;
        uint4* Al4 = (uint4*)(buf + 2048);
        uint2* Bh2 = (uint2*)(buf + 4096);
        uint2* Bl2 = (uint2*)(buf + 6144);

        #pragma unroll
        for (int i = 0; i < 2; i++) {
            int slot = warp + 8 * i;
            Ah4[slot * 32 + lane] = make_uint4(ra2[i][0].x, ra2[i][1].x, ra2[i][2].x, ra2[i][3].x);
            if (lo_on)
                Al4[slot * 32 + lane] = make_uint4(ra2[i][0].y, ra2[i][1].y, ra2[i][2].y, ra2[i][3].y);
        }
        #pragma unroll
        for (int j = 0; j < 4; j++) {
            int slot = (j >> 1) * 16 + warp + 8 * (j & 1);
            Bh2[slot * 32 + lane] = make_uint2(rb2[j][0].x, rb2[j][1].x);
            if (lo_on)
                Bl2[slot * 32 + lane] = make_uint2(rb2[j][0].y, rb2[j][1].y);
        }
        __syncthreads();

        if (s + 1 < S) {
            const int ub = (s + 1) << 4;
            #pragma unroll
            for (int i = 0; i < 2; i++) {
                int u0 = ub + 8 * i + tig;
                ra2[i][0] = A2[(size_t)arow * K2DIM + u0];
                ra2[i][1] = A2[(size_t)(arow + 8) * K2DIM + u0];
                ra2[i][2] = A2[(size_t)arow * K2DIM + u0 + 4];
                ra2[i][3] = A2[(size_t)(arow + 8) * K2DIM + u0 + 4];
            }
            #pragma unroll
            for (int j = 0; j < 4; j++) {
                int n = n0 + (warp + 8 * (j & 1)) * 8 + gid;
                int u0 = ub + (j >> 1) * 8 + tig;
                rb2[j][0] = B2[(size_t)n * K2DIM + u0];
                rb2[j][1] = B2[(size_t)n * K2DIM + u0 + 4];
            }
        }

        #pragma unroll
        for (int kk = 0; kk < 2; kk++) {
            uint4 ah[2], al[2];
            uint2 bh[8], bl[8];
            #pragma unroll
            for (int mf = 0; mf < 2; mf++) {
                int slot = kk * 8 + wm * 2 + mf;
                ah[mf] = Ah4[slot * 32 + lane];
                if (lo_on) al[mf] = Al4[slot * 32 + lane];
            }
            #pragma unroll
            for (int nf = 0; nf < 8; nf++) {
                int slot = kk * 16 + wn * 8 + nf;
                bh[nf] = Bh2[slot * 32 + lane];
                if (lo_on) bl[nf] = Bl2[slot * 32 + lane];
            }
            #pragma unroll
            for (int nf = 0; nf < 8; nf++)
                #pragma unroll
                for (int mf = 0; mf < 2; mf++)
                    MMA_F16(acc[mf][nf], ah[mf], bh[nf]);
            if (lo_on) {
                #pragma unroll
                for (int nf = 0; nf < 8; nf++)
                    #pragma unroll
                    for (int mf = 0; mf < 2; mf++)
                        MMA_F16(acc[mf][nf], ah[mf], bl[nf]);
                #pragma unroll
                for (int nf = 0; nf < 8; nf++)
                    #pragma unroll
                    for (int mf = 0; mf < 2; mf++)
                        MMA_F16(acc[mf][nf], al[mf], bh[nf]);
            }
        }
        __syncthreads();
    }

    if (EPI == 0) {
        #pragma unroll
        for (int mf = 0; mf < 2; mf++) {
            const int r0 = m0 + wm * 32 + mf * 16 + gid;
            #pragma unroll
            for (int nf = 0; nf < 8; nf++) {
                const int c = n0 + wn * 64 + nf * 8 + tig * 2;
                *(float2*)(C + (size_t)r0 * N + c) = make_float2(acc[mf][nf][0], acc[mf][nf][1]);
                *(float2*)(C + (size_t)(r0 + 8) * N + c) = make_float2(acc[mf][nf][2], acc[mf][nf][3]);
            }
        }
    } else {
        const int bx = blockIdx.x;
        if (bx < 16) {
            const int h = bx;
            #pragma unroll
            for (int mf = 0; mf < 2; mf++) {
                int rg = (m0 >> 4) + wm * 2 + mf;
                #pragma unroll
                for (int k2 = 0; k2 < 4; k2++) {
                    int kkg = wn * 4 + k2;
                    const float* e = acc[mf][2 * k2];
                    const float* o = acc[mf][2 * k2 + 1];
                    uint4 hv, lv;
                    cvt_h2(e[0], e[1], hv.x, lv.x);
                    cvt_h2(e[2], e[3], hv.y, lv.y);
                    cvt_h2(o[0], o[1], hv.z, lv.z);
                    cvt_h2(o[2], o[3], hv.w, lv.w);
                    size_t idx = ((size_t)(h * 128 + rg) * 8 + kkg) * 32 + lane;
                    g_qh4[idx] = hv;
                    g_ql4[idx] = lv;
                }
            }
        } else if (bx == 16) {
            #pragma unroll
            for (int mf = 0; mf < 2; mf++) {
                int j = m0 + wm * 32 + mf * 16 + gid;
                #pragma unroll
                for (int nf = 0; nf < 8; nf++) {
                    int d2 = wn * 32 + nf * 4 + tig;
                    unsigned h0, l0, h1, l1;
                    cvt_h2(acc[mf][nf][0], acc[mf][nf][1], h0, l0);
                    cvt_h2(acc[mf][nf][2], acc[mf][nf][3], h1, l1);
                    g_kt2[d2 * SEQ + j]     = make_uint2(h0, l0);
                    g_kt2[d2 * SEQ + j + 8] = make_uint2(h1, l1);
                }
            }
        } else {
            #pragma unroll
            for (int mf = 0; mf < 2; mf++) {
                int j = m0 + wm * 32 + mf * 16 + gid;
                #pragma unroll
                for (int nf = 0; nf < 8; nf++) {
                    int d = wn * 64 + nf * 8 + tig * 2;
                    *(float2*)&g_v[(size_t)j * DHEAD + d] =
                        make_float2(acc[mf][nf][0], acc[mf][nf][1]);
                    *(float2*)&g_v[(size_t)(j + 8) * DHEAD + d] =
                        make_float2(acc[mf][nf][2], acc[mf][nf][3]);
                }
            }
        }
    }
}

// ---------------- V j-paired interleaved half2 planes --------------------------
__global__ void vprep_kernel() {
    int t = blockIdx.x * 256 + threadIdx.x;     // 131072
    int d = t & 127, j2 = t >> 7;
    float v0 = g_v[(size_t)(2 * j2) * DHEAD + d];
    float v1 = g_v[(size_t)(2 * j2 + 1) * DHEAD + d];
    unsigned h, l;
    cvt_h2(v0, v1, h, l);
    g_vt2[j2 * DHEAD + d] = make_uint2(h, l);
}

// ---------------- V suffix sums ------------------------------------------------
__global__ void vpart_kernel() {
    int blk = blockIdx.x, d = threadIdx.x;
    float s = 0.f;
    #pragma unroll 8
    for (int r = 0; r < 128; r++)
        s += g_v[(size_t)(blk * 128 + r) * DHEAD + d];
    g_vpart[blk * DHEAD + d] = s;
}
__global__ void vsuf_kernel() {
    int blk = blockIdx.x, d = threadIdx.x;
    float acc = 0.f;
    for (int b = blk + 1; b < 16; b++) acc += g_vpart[b * DHEAD + d];
    #pragma unroll 4
    for (int r = 127; r >= 0; r--) {
        int row = blk * 128 + r;
        g_vsuf[(size_t)row * DHEAD + d] = acc;
        acc += g_v[(size_t)row * DHEAD + d];
    }
}

// ---------------- row-owning fp16 tensor-core flash attention -------------------
// QK x3; PV 1-term.  P in registers; softmax warp-local.  Synchronous tile loads
// (R13-proven path; cp.async variant measured slower in R14).
__global__ __launch_bounds__(256, 1) void attn_mma_kernel(const float* __restrict__ pos_bias) {
    extern __shared__ float sm[];
    uint2* Kint = (uint2*)sm;
    uint2* Vint = (uint2*)sm + 4352;

    const int h  = blockIdx.y;
    const int ib = gridDim.x - 1 - blockIdx.x;
    const int i0 = ib * 128;
    const int tid = threadIdx.x, lane = tid & 31, warp = tid >> 5;
    const int gid = lane >> 2, tig = lane & 3;

    const int rg = (i0 >> 4) + warp;
    const size_t qbase = ((size_t)(h * 128 + rg) * 8) * 32 + lane;

    const int jl = tid & 63, cb = tid >> 6;
    const int r0g = i0 + warp * 16 + gid, r1g = r0g + 8;
    const int jd = 2 * ib + (warp >> 2);
    const int jbmax = 2 * ib + 1;

    float o[16][4];
    #pragma unroll
    for (int nf = 0; nf < 16; nf++)
        #pragma unroll
        for (int q = 0; q < 4; q++) o[nf][q] = 0.f;
    float m0 = -1e30f, m1 = -1e30f, l0 = 0.f, l1 = 0.f;

    for (int jb = 0; jb <= jbmax; jb++) {
        const int j0 = jb * 64;
        __syncthreads();
        #pragma unroll
        for (int it = 0; it < 16; it++) {
            int d2 = cb * 16 + it;
            Kint[d2 * 68 + jl] = g_kt2[d2 * SEQ + j0 + jl];
        }
        #pragma unroll
        for (int it = 0; it < 16; it++) {
            int idx = it * 256 + tid;
            int j2 = idx >> 7, d = idx & 127;
            Vint[j2 * 132 + d] = g_vt2[(j0 / 2 + j2) * DHEAD + d];
        }
        __syncthreads();

        if (jb > jd) continue;

        float s[8][4];
        #pragma unroll
        for (int nf = 0; nf < 8; nf++)
            #pragma unroll
            for (int q = 0; q < 4; q++) s[nf][q] = 0.f;

        #pragma unroll
        for (int kk = 0; kk < 8; kk++) {
            uint4 qh = g_qh4[qbase + kk * 32];
            uint4 ql = g_ql4[qbase + kk * 32];
            const int kr0 = (kk * 8 + tig) * 68, kr1 = kr0 + 4 * 68;
            uint2 bh[8], bl[8];
            #pragma unroll
            for (int nf = 0; nf < 8; nf++) {
                int col = nf * 8 + gid;
                uint2 kv0 = Kint[kr0 + col];
                uint2 kv1 = Kint[kr1 + col];
                bh[nf] = make_uint2(kv0.x, kv1.x);
                bl[nf] = make_uint2(kv0.y, kv1.y);
            }
            #pragma unroll
            for (int nf = 0; nf < 8; nf++) MMA_F16(s[nf], qh, bh[nf]);
            #pragma unroll
            for (int nf = 0; nf < 8; nf++) MMA_F16(s[nf], qh, bl[nf]);
            #pragma unroll
            for (int nf = 0; nf < 8; nf++) MMA_F16(s[nf], ql, bh[nf]);
        }

        const float* pb0 = pos_bias + ((size_t)h * SEQ + r0g) * SEQ + j0 + tig * 2;
        const float* pb1 = pb0 + (size_t)8 * SEQ;
        #pragma unroll
        for (int nf = 0; nf < 8; nf++) {
            float2 b0 = *(const float2*)(pb0 + nf * 8);
            float2 b1 = *(const float2*)(pb1 + nf * 8);
            s[nf][0] += b0.x; s[nf][1] += b0.y;
            s[nf][2] += b1.x; s[nf][3] += b1.y;
        }
        if (jb == jd) {
            #pragma unroll
            for (int nf = 0; nf < 8; nf++) {
                int c = j0 + nf * 8 + tig * 2;
                if (c > r0g)     s[nf][0] = -1e30f;
                if (c + 1 > r0g) s[nf][1] = -1e30f;
                if (c > r1g)     s[nf][2] = -1e30f;
                if (c + 1 > r1g) s[nf][3] = -1e30f;
            }
        }

        float rm0 = -1e30f, rm1 = -1e30f;
        #pragma unroll
        for (int nf = 0; nf < 8; nf++) {
            rm0 = fmaxf(rm0, fmaxf(s[nf][0], s[nf][1]));
            rm1 = fmaxf(rm1, fmaxf(s[nf][2], s[nf][3]));
        }
        rm0 = fmaxf(rm0, __shfl_xor_sync(0xffffffffu, rm0, 1));
        rm0 = fmaxf(rm0, __shfl_xor_sync(0xffffffffu, rm0, 2));
        rm1 = fmaxf(rm1, __shfl_xor_sync(0xffffffffu, rm1, 1));
        rm1 = fmaxf(rm1, __shfl_xor_sync(0xffffffffu, rm1, 2));
        float mn0 = fmaxf(m0, rm0), mn1 = fmaxf(m1, rm1);
        float sc0 = __expf(m0 - mn0), sc1 = __expf(m1 - mn1);

        float rs0 = 0.f, rs1 = 0.f;
        uint4 pah[4];
        #pragma unroll
        for (int c = 0; c < 4; c++) {
            float p00 = __expf(s[2*c][0] - mn0);
            float p01 = __expf(s[2*c][1] - mn0);
            float p02 = __expf(s[2*c][2] - mn1);
            float p03 = __expf(s[2*c][3] - mn1);
            float p10 = __expf(s[2*c+1][0] - mn0);
            float p11 = __expf(s[2*c+1][1] - mn0);
            float p12 = __expf(s[2*c+1][2] - mn1);
            float p13 = __expf(s[2*c+1][3] - mn1);
            rs0 += p00 + p01 + p10 + p11;
            rs1 += p02 + p03 + p12 + p13;
            pah[c].x = cvt_h(p00, p01);
            pah[c].y = cvt_h(p02, p03);
            pah[c].z = cvt_h(p10, p11);
            pah[c].w = cvt_h(p12, p13);
        }
        rs0 += __shfl_xor_sync(0xffffffffu, rs0, 1);
        rs0 += __shfl_xor_sync(0xffffffffu, rs0, 2);
        rs1 += __shfl_xor_sync(0xffffffffu, rs1, 1);
        rs1 += __shfl_xor_sync(0xffffffffu, rs1, 2);
        l0 = l0 * sc0 + rs0;
        l1 = l1 * sc1 + rs1;
        m0 = mn0; m1 = mn1;

        #pragma unroll
        for (int nf = 0; nf < 16; nf++) {
            o[nf][0] *= sc0; o[nf][1] *= sc0;
            o[nf][2] *= sc1; o[nf][3] *= sc1;
        }
        #pragma unroll
        for (int c = 0; c < 4; c++) {
            const int vr0 = (c * 8 + tig) * 132, vr1 = vr0 + 4 * 132;
            #pragma unroll
            for (int nf = 0; nf < 16; nf++) {
                int dcol = nf * 8 + gid;
                uint2 bh = make_uint2(Vint[vr0 + dcol].x, Vint[vr1 + dcol].x);
                MMA_F16(o[nf], pah[c], bh);
            }
        }
    }

    float cnt0 = (float)(SEQ - 1 - r0g), cnt1 = (float)(SEQ - 1 - r1g);
    float mf0 = fmaxf(m0, MASKVF), mf1 = fmaxf(m1, MASKVF);
    float wu0 = __expf(m0 - mf0),  wu1 = __expf(m1 - mf1);
    float wk0 = __expf(MASKVF - mf0), wk1 = __expf(MASKVF - mf1);
    float iZ0 = 1.f / (l0 * wu0 + cnt0 * wk0);
    float iZ1 = 1.f / (l1 * wu1 + cnt1 * wk1);
    #pragma unroll
    for (int nf = 0; nf < 16; nf++) {
        int dcol = nf * 8 + tig * 2;
        float2 vs0 = *(const float2*)&g_vsuf[(size_t)r0g * DHEAD + dcol];
        float2 vs1 = *(const float2*)&g_vsuf[(size_t)r1g * DHEAD + dcol];
        float o00 = (o[nf][0] * wu0 + wk0 * vs0.x) * iZ0;
        float o01 = (o[nf][1] * wu0 + wk0 * vs0.y) * iZ0;
        float o10 = (o[nf][2] * wu1 + wk1 * vs1.x) * iZ1;
        float o11 = (o[nf][3] * wu1 + wk1 * vs1.y) * iZ1;
        unsigned hw, lw;
        size_t u = (size_t)(h * DHEAD + dcol) >> 1;
        cvt_h2(o00, o01, hw, lw);
        g_ao2[(size_t)r0g * K2DIM + u] = make_uint2(hw, lw);
        cvt_h2(o10, o11, hw, lw);
        g_ao2[(size_t)r1g * K2DIM + u] = make_uint2(hw, lw);
    }
}

// ---------------- launch ---------------------------------------------------------
extern "C" void kernel_launch(void* const* d_in, const int* in_sizes, int n_in,
                              void* d_out, int out_size) {
    (void)in_sizes; (void)n_in; (void)out_size;
    const float* x        = (const float*)d_in[0];
    const float* pos_bias = (const float*)d_in[1];
    const float* gamma    = (const float*)d_in[2];
    const float* wq       = (const float*)d_in[3];
    const float* wk       = (const float*)d_in[4];
    const float* wv       = (const float*)d_in[5];
    const float* wo       = (const float*)d_in[6];
    float* out = (float*)d_out;

    uint2 *xn2_p, *wc2_p, *wo2_p, *ao2_p;
    cudaGetSymbolAddress((void**)&xn2_p, g_xn2);
    cudaGetSymbolAddress((void**)&wc2_p, g_wc2);
    cudaGetSymbolAddress((void**)&wo2_p, g_wo2);
    cudaGetSymbolAddress((void**)&ao2_p, g_ao2);

    const int GEMM_SMEM = 2 * 8192 * 4;      // 65536
    const int ATTN_SMEM = 8576 * 8;          // 68608 (Kint + Vint, uint2)
    cudaFuncSetAttribute((const void*)gemm_h2_kernel<0, 1>, cudaFuncAttributeMaxDynamicSharedMemorySize, GEMM_SMEM);
    cudaFuncSetAttribute((const void*)gemm_h2_kernel<1, 3>, cudaFuncAttributeMaxDynamicSharedMemorySize, GEMM_SMEM);
    cudaFuncSetAttribute((const void*)attn_mma_kernel, cudaFuncAttributeMaxDynamicSharedMemorySize, ATTN_SMEM);

    dim3 tb(32, 8);
    transpose_split_all_kernel<<<8704, tb>>>(wq, wk, wv, wo, wc2_p, wo2_p);

    rmsnorm_split_kernel<<<SEQ, 256>>>(x, gamma);

    gemm_h2_kernel<1, 3><<<dim3(18, 16), 256, GEMM_SMEM>>>(xn2_p, wc2_p, nullptr, QKVN);

    vprep_kernel<<<512, 256>>>();
    vpart_kernel<<<16, 128>>>();
    vsuf_kernel<<<16, 128>>>();

    attn_mma_kernel<<<dim3(16, HEADS), 256, ATTN_SMEM>>>(pos_bias);

    gemm_h2_kernel<0, 1><<<dim3(16, 16), 256, GEMM_SMEM>>>(ao2_p, wo2_p, out, DIMM);
}

// round 16
// speedup vs baseline: 1.0861x; 1.0765x over previous
#include <cuda_runtime.h>
#include <cuda_fp16.h>
#include <math.h>
#include <stddef.h>
#include <stdint.h>

#define SEQ    2048
#define DIMM   2048
#define HEADS  16
#define DHEAD  128
#define QKVN   2304
#define K2DIM  1024          // K/2 half2 units per row
#define EPSF   1e-5f
#define MASKVF 1e-10f
#define SCALEF 0.08838834764831845f

// ---------------- scratch ------------------------------------------------------
__device__ uint2    g_xn2[SEQ * K2DIM];
__device__ uint2    g_wc2[QKVN * K2DIM];     // [wq|wk|wv]^T (q pre-scaled)
__device__ uint2    g_wo2[DIMM * K2DIM];
__device__ uint2    g_ao2[SEQ * K2DIM];
__device__ uint4    g_qh4[HEADS * 128 * 8 * 32];   // Q fragments hi
__device__ uint4    g_ql4[HEADS * 128 * 8 * 32];   // Q fragments lo
__device__ uint4    g_kp4[32 * SEQ];         // K^T pair-packed: {h(d2),l(d2),h(d2+4),l(d2+4)}
__device__ float    g_v[SEQ * DHEAD];        // V dense fp32
__device__ uint2    g_vp[512 * DHEAD];       // V hi pair-packed: {hi(j2),hi(j2+4)}
__device__ float    g_vsuf[SEQ * DHEAD];
__device__ float    g_vpart[16 * DHEAD];

// ---------------- helpers -------------------------------------------------------
__device__ __forceinline__ void cvt_h2(float x0, float x1, unsigned& h, unsigned& l) {
    __half2 hh = __floats2half2_rn(x0, x1);
    __half2 ll = __floats2half2_rn(x0 - __low2float(hh), x1 - __high2float(hh));
    h = *reinterpret_cast<unsigned*>(&hh);
    l = *reinterpret_cast<unsigned*>(&ll);
}
__device__ __forceinline__ unsigned cvt_h(float x0, float x1) {
    __half2 hh = __floats2half2_rn(x0, x1);
    return *reinterpret_cast<unsigned*>(&hh);
}
#define MMA_F16(Cacc, Av, Bv)                                               \
    asm volatile("mma.sync.aligned.m16n8k16.row.col.f32.f16.f16.f32 "       \
        "{%0,%1,%2,%3}, {%4,%5,%6,%7}, {%8,%9}, {%0,%1,%2,%3};"             \
        : "+f"((Cacc)[0]), "+f"((Cacc)[1]), "+f"((Cacc)[2]), "+f"((Cacc)[3])\
        : "r"((Av).x), "r"((Av).y), "r"((Av).z), "r"((Av).w),               \
          "r"((Bv).x), "r"((Bv).y))

// ---------------- RMSNorm -> interleaved half2 hi/lo ------------------------------
__global__ void rmsnorm_split_kernel(const float* __restrict__ x,
                                     const float* __restrict__ gamma) {
    int row = blockIdx.x;
    const float* xr = x + (size_t)row * DIMM;
    float ss = 0.f;
    for (int i = threadIdx.x; i < DIMM; i += 256) { float v = xr[i]; ss += v * v; }
    __shared__ float red[8];
    #pragma unroll
    for (int o = 16; o; o >>= 1) ss += __shfl_xor_sync(0xffffffffu, ss, o);
    if ((threadIdx.x & 31) == 0) red[threadIdx.x >> 5] = ss;
    __syncthreads();
    if (threadIdx.x < 32) {
        float v = (threadIdx.x < 8) ? red[threadIdx.x] : 0.f;
        #pragma unroll
        for (int o = 4; o; o >>= 1) v += __shfl_xor_sync(0xffffffffu, v, o);
        if (threadIdx.x == 0) red[0] = v;
    }
    __syncthreads();
    float inv = rsqrtf(red[0] / (float)DIMM + EPSF);
    for (int u = threadIdx.x; u < K2DIM; u += 256) {
        float2 xv = *(const float2*)(xr + 2 * u);
        float2 gv = *(const float2*)(gamma + 2 * u);
        unsigned h, l;
        cvt_h2(xv.x * inv * gv.x, xv.y * inv * gv.y, h, l);
        g_xn2[(size_t)row * K2DIM + u] = make_uint2(h, l);
    }
}

// ---------------- fused transpose + split for all 4 weights -----------------------
__global__ void transpose_split_all_kernel(const float* __restrict__ wq,
                                           const float* __restrict__ wk,
                                           const float* __restrict__ wv,
                                           const float* __restrict__ wo,
                                           uint2* __restrict__ wc2,
                                           uint2* __restrict__ wo2) {
    __shared__ float tile[32][33];
    int b = blockIdx.x;
    const float* src; uint2* dst; int C; float scale; int bx, by;
    if (b < 4096)      { src = wq; dst = wc2;                       C = DIMM;  scale = SCALEF;
                         bx = (b & 63) * 32;        by = (b >> 6) * 32; }
    else if (b < 4352) { int t = b - 4096; src = wk; dst = wc2 + (size_t)2048 * K2DIM; C = DHEAD; scale = 1.f;
                         bx = (t & 3) * 32;         by = (t >> 2) * 32; }
    else if (b < 4608) { int t = b - 4352; src = wv; dst = wc2 + (size_t)2176 * K2DIM; C = DHEAD; scale = 1.f;
                         bx = (t & 3) * 32;         by = (t >> 2) * 32; }
    else               { int t = b - 4608; src = wo; dst = wo2;     C = DIMM;  scale = 1.f;
                         bx = (t & 63) * 32;        by = (t >> 6) * 32; }

    int tx = threadIdx.x, ty = threadIdx.y;           // 32 x 8
    #pragma unroll
    for (int j = 0; j < 32; j += 8)
        tile[ty + j][tx] = src[(size_t)(by + ty + j) * C + bx + tx];
    __syncthreads();
    int ul = tx & 15, nb = ty * 2 + (tx >> 4);
    #pragma unroll
    for (int rep = 0; rep < 2; rep++) {
        int nl = nb + rep * 16;
        float v0 = tile[2 * ul][nl] * scale;
        float v1 = tile[2 * ul + 1][nl] * scale;
        unsigned h, l;
        cvt_h2(v0, v1, h, l);
        dst[(size_t)(bx + nl) * K2DIM + (by >> 1) + ul] = make_uint2(h, l);
    }
}

// ---------------- fp16 split GEMM (compile-time term set) -------------------------
// TERMS: 3 = ah*bh + ah*bl + al*bh; 1 = ah*bh (pure fp16).
template <int EPI, int TERMS>
__global__ __launch_bounds__(256) void gemm_h2_kernel(
    const uint2* __restrict__ A2, const uint2* __restrict__ B2,
    float* __restrict__ C, int N)
{
    extern __shared__ unsigned smu[];
    const int tid = threadIdx.x, lane = tid & 31, warp = tid >> 5;
    const int m0 = blockIdx.y << 7, n0 = blockIdx.x << 7;
    const int wm = warp >> 1, wn = warp & 1;
    const int gid = lane >> 2, tig = lane & 3;

    float acc[2][8][4];
    #pragma unroll
    for (int mf = 0; mf < 2; mf++)
        #pragma unroll
        for (int nf = 0; nf < 8; nf++)
            #pragma unroll
            for (int q = 0; q < 4; q++) acc[mf][nf][q] = 0.f;

    uint2 ra2[2][4], rb2[4][2];
    const int arow = m0 + warp * 16 + gid;

    #pragma unroll
    for (int i = 0; i < 2; i++) {
        int u0 = 8 * i + tig;
        ra2[i][0] = A2[(size_t)arow * K2DIM + u0];
        ra2[i][1] = A2[(size_t)(arow + 8) * K2DIM + u0];
        ra2[i][2] = A2[(size_t)arow * K2DIM + u0 + 4];
        ra2[i][3] = A2[(size_t)(arow + 8) * K2DIM + u0 + 4];
    }
    #pragma unroll
    for (int j = 0; j < 4; j++) {
        int n = n0 + (warp + 8 * (j & 1)) * 8 + gid;
        int u0 = (j >> 1) * 8 + tig;
        rb2[j][0] = B2[(size_t)n * K2DIM + u0];
        rb2[j][1] = B2[(size_t)n * K2DIM + u0 + 4];
    }

    const int S = 64;
    for (int s = 0; s < S; s++) {
        unsigned* buf = smu + (s & 1) * 8192;
        uint4* Ah4 = (uint4*)buf;
        uint4* Al4 = (uint4*)(buf + 2048);
        uint2* Bh2 = (uint2*)(buf + 4096);
        uint2* Bl2 = (uint2*)(buf + 6144);

        #pragma unroll
        for (int i = 0; i < 2; i++) {
            int slot = warp + 8 * i;
            Ah4[slot * 32 + lane] = make_uint4(ra2[i][0].x, ra2[i][1].x, ra2[i][2].x, ra2[i][3].x);
            if (TERMS == 3)
                Al4[slot * 32 + lane] = make_uint4(ra2[i][0].y, ra2[i][1].y, ra2[i][2].y, ra2[i][3].y);
        }
        #pragma unroll
        for (int j = 0; j < 4; j++) {
            int slot = (j >> 1) * 16 + warp + 8 * (j & 1);
            Bh2[slot * 32 + lane] = make_uint2(rb2[j][0].x, rb2[j][1].x);
            if (TERMS == 3)
                Bl2[slot * 32 + lane] = make_uint2(rb2[j][0].y, rb2[j][1].y);
        }
        __syncthreads();

        if (s + 1 < S) {
            const int ub = (s + 1) << 4;
            #pragma unroll
            for (int i = 0; i < 2; i++) {
                int u0 = ub + 8 * i + tig;
                ra2[i][0] = A2[(size_t)arow * K2DIM + u0];
                ra2[i][1] = A2[(size_t)(arow + 8) * K2DIM + u0];
                ra2[i][2] = A2[(size_t)arow * K2DIM + u0 + 4];
                ra2[i][3] = A2[(size_t)(arow + 8) * K2DIM + u0 + 4];
            }
            #pragma unroll
            for (int j = 0; j < 4; j++) {
                int n = n0 + (warp + 8 * (j & 1)) * 8 + gid;
                int u0 = ub + (j >> 1) * 8 + tig;
                rb2[j][0] = B2[(size_t)n * K2DIM + u0];
                rb2[j][1] = B2[(size_t)n * K2DIM + u0 + 4];
            }
        }

        #pragma unroll
        for (int kk = 0; kk < 2; kk++) {
            uint4 ah[2], al[2];
            uint2 bh[8], bl[8];
            #pragma unroll
            for (int mf = 0; mf < 2; mf++) {
                int slot = kk * 8 + wm * 2 + mf;
                ah[mf] = Ah4[slot * 32 + lane];
                if (TERMS == 3) al[mf] = Al4[slot * 32 + lane];
            }
            #pragma unroll
            for (int nf = 0; nf < 8; nf++) {
                int slot = kk * 16 + wn * 8 + nf;
                bh[nf] = Bh2[slot * 32 + lane];
                if (TERMS == 3) bl[nf] = Bl2[slot * 32 + lane];
            }
            #pragma unroll
            for (int nf = 0; nf < 8; nf++)
                #pragma unroll
                for (int mf = 0; mf < 2; mf++)
                    MMA_F16(acc[mf][nf], ah[mf], bh[nf]);
            if (TERMS == 3) {
                #pragma unroll
                for (int nf = 0; nf < 8; nf++)
                    #pragma unroll
                    for (int mf = 0; mf < 2; mf++)
                        MMA_F16(acc[mf][nf], ah[mf], bl[nf]);
                #pragma unroll
                for (int nf = 0; nf < 8; nf++)
                    #pragma unroll
                    for (int mf = 0; mf < 2; mf++)
                        MMA_F16(acc[mf][nf], al[mf], bh[nf]);
            }
        }
        __syncthreads();
    }

    if (EPI == 0) {
        #pragma unroll
        for (int mf = 0; mf < 2; mf++) {
            const int r0 = m0 + wm * 32 + mf * 16 + gid;
            #pragma unroll
            for (int nf = 0; nf < 8; nf++) {
                const int c = n0 + wn * 64 + nf * 8 + tig * 2;
                *(float2*)(C + (size_t)r0 * N + c) = make_float2(acc[mf][nf][0], acc[mf][nf][1]);
                *(float2*)(C + (size_t)(r0 + 8) * N + c) = make_float2(acc[mf][nf][2], acc[mf][nf][3]);
            }
        }
    } else {
        const int bx = blockIdx.x;
        if (bx < 16) {
            const int h = bx;
            #pragma unroll
            for (int mf = 0; mf < 2; mf++) {
                int rg = (m0 >> 4) + wm * 2 + mf;
                #pragma unroll
                for (int k2 = 0; k2 < 4; k2++) {
                    int kkg = wn * 4 + k2;
                    const float* e = acc[mf][2 * k2];
                    const float* o = acc[mf][2 * k2 + 1];
                    uint4 hv, lv;
                    cvt_h2(e[0], e[1], hv.x, lv.x);
                    cvt_h2(e[2], e[3], hv.y, lv.y);
                    cvt_h2(o[0], o[1], hv.z, lv.z);
                    cvt_h2(o[2], o[3], hv.w, lv.w);
                    size_t idx = ((size_t)(h * 128 + rg) * 8 + kkg) * 32 + lane;
                    g_qh4[idx] = hv;
                    g_ql4[idx] = lv;
                }
            }
        } else if (bx == 16) {
            // K: pair-packed uint4 {h(d2), l(d2), h(d2+4), l(d2+4)}, d2 pairs (nf=2c, 2c+1)
            #pragma unroll
            for (int mf = 0; mf < 2; mf++) {
                int j = m0 + wm * 32 + mf * 16 + gid;
                #pragma unroll
                for (int c = 0; c < 4; c++) {
                    const float* e = acc[mf][2 * c];      // d2 = wn*32 + 8c + tig
                    const float* o = acc[mf][2 * c + 1];  // d2 + 4
                    int pidx = wn * 16 + c * 4 + tig;
                    uint4 vj, vj8;
                    cvt_h2(e[0], e[1], vj.x, vj.y);
                    cvt_h2(o[0], o[1], vj.z, vj.w);
                    cvt_h2(e[2], e[3], vj8.x, vj8.y);
                    cvt_h2(o[2], o[3], vj8.z, vj8.w);
                    g_kp4[(size_t)pidx * SEQ + j]     = vj;
                    g_kp4[(size_t)pidx * SEQ + j + 8] = vj8;
                }
            }
        } else {
            #pragma unroll
            for (int mf = 0; mf < 2; mf++) {
                int j = m0 + wm * 32 + mf * 16 + gid;
                #pragma unroll
                for (int nf = 0; nf < 8; nf++) {
                    int d = wn * 64 + nf * 8 + tig * 2;
                    *(float2*)&g_v[(size_t)j * DHEAD + d] =
                        make_float2(acc[mf][nf][0], acc[mf][nf][1]);
                    *(float2*)&g_v[(size_t)(j + 8) * DHEAD + d] =
                        make_float2(acc[mf][nf][2], acc[mf][nf][3]);
                }
            }
        }
    }
}

// ---------------- V pair-packed hi planes -----------------------------------------
// g_vp[pi * DHEAD + d] = {hi(j2a), hi(j2a+4)}, pi = (j2a>>3)*4 + (j2a&3), j2a&7 < 4
__global__ void vprep_kernel() {
    int t = blockIdx.x * 256 + threadIdx.x;     // 65536 total
    int d = t & 127, pi = t >> 7;               // pi 0..511
    int j2a = (pi >> 2) * 8 + (pi & 3);
    int j2b = j2a + 4;
    unsigned ha = cvt_h(g_v[(size_t)(2 * j2a) * DHEAD + d],
                        g_v[(size_t)(2 * j2a + 1) * DHEAD + d]);
    unsigned hb = cvt_h(g_v[(size_t)(2 * j2b) * DHEAD + d],
                        g_v[(size_t)(2 * j2b + 1) * DHEAD + d]);
    g_vp[pi * DHEAD + d] = make_uint2(ha, hb);
}

// ---------------- V suffix sums ----------------------------------------------------
__global__ void vpart_kernel() {
    int blk = blockIdx.x, d = threadIdx.x;
    float s = 0.f;
    #pragma unroll 8
    for (int r = 0; r < 128; r++)
        s += g_v[(size_t)(blk * 128 + r) * DHEAD + d];
    g_vpart[blk * DHEAD + d] = s;
}
__global__ void vsuf_kernel() {
    int blk = blockIdx.x, d = threadIdx.x;
    float acc = 0.f;
    for (int b = blk + 1; b < 16; b++) acc += g_vpart[b * DHEAD + d];
    #pragma unroll 4
    for (int r = 127; r >= 0; r--) {
        int row = blk * 128 + r;
        g_vsuf[(size_t)row * DHEAD + d] = acc;
        acc += g_v[(size_t)row * DHEAD + d];
    }
}

// ---------------- row-owning fp16 tensor-core flash attention ----------------------
// QK x3 (pair-packed LDS.128); PV 1-term (pair-packed LDS.64).
// smem: Kp4s[32][66] uint4 @0 (33792 B), Vps[16][132] uint2 @8448 floats (16896 B).
__global__ __launch_bounds__(256, 1) void attn_mma_kernel(const float* __restrict__ pos_bias) {
    extern __shared__ float sm[];
    uint4* Kp4s = (uint4*)sm;
    uint2* Vps  = (uint2*)(sm + 8448);

    const int h  = blockIdx.y;
    const int ib = gridDim.x - 1 - blockIdx.x;
    const int i0 = ib * 128;
    const int tid = threadIdx.x, lane = tid & 31, warp = tid >> 5;
    const int gid = lane >> 2, tig = lane & 3;

    const int rg = (i0 >> 4) + warp;
    const size_t qbase = ((size_t)(h * 128 + rg) * 8) * 32 + lane;

    const int jl = tid & 63, cb = tid >> 6;
    const int r0g = i0 + warp * 16 + gid, r1g = r0g + 8;
    const int jd = 2 * ib + (warp >> 2);
    const int jbmax = 2 * ib + 1;

    float o[16][4];
    #pragma unroll
    for (int nf = 0; nf < 16; nf++)
        #pragma unroll
        for (int q = 0; q < 4; q++) o[nf][q] = 0.f;
    float m0 = -1e30f, m1 = -1e30f, l0 = 0.f, l1 = 0.f;

    for (int jb = 0; jb <= jbmax; jb++) {
        const int j0 = jb * 64;
        __syncthreads();
        // K tile: 32 pairs x 64 j, uint4, stride 66 (conflict-free LDS.128)
        #pragma unroll
        for (int it = 0; it < 8; it++) {
            int p = cb * 8 + it;
            Kp4s[p * 66 + jl] = g_kp4[(size_t)p * SEQ + j0 + jl];
        }
        // V tile: 16 pairs x 128 d, uint2, stride 132 (conflict-free LDS.64)
        #pragma unroll
        for (int it = 0; it < 8; it++) {
            int idx = it * 256 + tid;
            int pl = idx >> 7, d = idx & 127;
            int pig = ((j0 >> 4) + (pl >> 2)) * 4 + (pl & 3);
            Vps[pl * 132 + d] = g_vp[pig * DHEAD + d];
        }
        __syncthreads();

        if (jb > jd) continue;

        float s[8][4];
        #pragma unroll
        for (int nf = 0; nf < 8; nf++)
            #pragma unroll
            for (int q = 0; q < 4; q++) s[nf][q] = 0.f;

        #pragma unroll
        for (int kk = 0; kk < 8; kk++) {
            uint4 qh = g_qh4[qbase + kk * 32];
            uint4 ql = g_ql4[qbase + kk * 32];
            const int kr = (kk * 4 + tig) * 66;
            uint2 bh[8], bl[8];
            #pragma unroll
            for (int nf = 0; nf < 8; nf++) {
                uint4 kq = Kp4s[kr + nf * 8 + gid];
                bh[nf] = make_uint2(kq.x, kq.z);
                bl[nf] = make_uint2(kq.y, kq.w);
            }
            #pragma unroll
            for (int nf = 0; nf < 8; nf++) MMA_F16(s[nf], qh, bh[nf]);
            #pragma unroll
            for (int nf = 0; nf < 8; nf++) MMA_F16(s[nf], qh, bl[nf]);
            #pragma unroll
            for (int nf = 0; nf < 8; nf++) MMA_F16(s[nf], ql, bh[nf]);
        }

        const float* pb0 = pos_bias + ((size_t)h * SEQ + r0g) * SEQ + j0 + tig * 2;
        const float* pb1 = pb0 + (size_t)8 * SEQ;
        #pragma unroll
        for (int nf = 0; nf < 8; nf++) {
            float2 b0 = *(const float2*)(pb0 + nf * 8);
            float2 b1 = *(const float2*)(pb1 + nf * 8);
            s[nf][0] += b0.x; s[nf][1] += b0.y;
            s[nf][2] += b1.x; s[nf][3] += b1.y;
        }
        if (jb == jd) {
            #pragma unroll
            for (int nf = 0; nf < 8; nf++) {
                int c = j0 + nf * 8 + tig * 2;
                if (c > r0g)     s[nf][0] = -1e30f;
                if (c + 1 > r0g) s[nf][1] = -1e30f;
                if (c > r1g)     s[nf][2] = -1e30f;
                if (c + 1 > r1g) s[nf][3] = -1e30f;
            }
        }

        float rm0 = -1e30f, rm1 = -1e30f;
        #pragma unroll
        for (int nf = 0; nf < 8; nf++) {
            rm0 = fmaxf(rm0, fmaxf(s[nf][0], s[nf][1]));
            rm1 = fmaxf(rm1, fmaxf(s[nf][2], s[nf][3]));
        }
        rm0 = fmaxf(rm0, __shfl_xor_sync(0xffffffffu, rm0, 1));
        rm0 = fmaxf(rm0, __shfl_xor_sync(0xffffffffu, rm0, 2));
        rm1 = fmaxf(rm1, __shfl_xor_sync(0xffffffffu, rm1, 1));
        rm1 = fmaxf(rm1, __shfl_xor_sync(0xffffffffu, rm1, 2));
        float mn0 = fmaxf(m0, rm0), mn1 = fmaxf(m1, rm1);
        float sc0 = __expf(m0 - mn0), sc1 = __expf(m1 - mn1);

        float rs0 = 0.f, rs1 = 0.f;
        uint4 pah[4];
        #pragma unroll
        for (int c = 0; c < 4; c++) {
            float p00 = __expf(s[2*c][0] - mn0);
            float p01 = __expf(s[2*c][1] - mn0);
            float p02 = __expf(s[2*c][2] - mn1);
            float p03 = __expf(s[2*c][3] - mn1);
            float p10 = __expf(s[2*c+1][0] - mn0);
            float p11 = __expf(s[2*c+1][1] - mn0);
            float p12 = __expf(s[2*c+1][2] - mn1);
            float p13 = __expf(s[2*c+1][3] - mn1);
            rs0 += p00 + p01 + p10 + p11;
            rs1 += p02 + p03 + p12 + p13;
            pah[c].x = cvt_h(p00, p01);
            pah[c].y = cvt_h(p02, p03);
            pah[c].z = cvt_h(p10, p11);
            pah[c].w = cvt_h(p12, p13);
        }
        rs0 += __shfl_xor_sync(0xffffffffu, rs0, 1);
        rs0 += __shfl_xor_sync(0xffffffffu, rs0, 2);
        rs1 += __shfl_xor_sync(0xffffffffu, rs1, 1);
        rs1 += __shfl_xor_sync(0xffffffffu, rs1, 2);
        l0 = l0 * sc0 + rs0;
        l1 = l1 * sc1 + rs1;
        m0 = mn0; m1 = mn1;

        #pragma unroll
        for (int nf = 0; nf < 16; nf++) {
            o[nf][0] *= sc0; o[nf][1] *= sc0;
            o[nf][2] *= sc1; o[nf][3] *= sc1;
        }
        #pragma unroll
        for (int c = 0; c < 4; c++) {
            const int vr = (c * 4 + tig) * 132;
            #pragma unroll
            for (int nf = 0; nf < 16; nf++) {
                uint2 bh = Vps[vr + nf * 8 + gid];
                MMA_F16(o[nf], pah[c], bh);
            }
        }
    }

    float cnt0 = (float)(SEQ - 1 - r0g), cnt1 = (float)(SEQ - 1 - r1g);
    float mf0 = fmaxf(m0, MASKVF), mf1 = fmaxf(m1, MASKVF);
    float wu0 = __expf(m0 - mf0),  wu1 = __expf(m1 - mf1);
    float wk0 = __expf(MASKVF - mf0), wk1 = __expf(MASKVF - mf1);
    float iZ0 = 1.f / (l0 * wu0 + cnt0 * wk0);
    float iZ1 = 1.f / (l1 * wu1 + cnt1 * wk1);
    #pragma unroll
    for (int nf = 0; nf < 16; nf++) {
        int dcol = nf * 8 + tig * 2;
        float2 vs0 = *(const float2*)&g_vsuf[(size_t)r0g * DHEAD + dcol];
        float2 vs1 = *(const float2*)&g_vsuf[(size_t)r1g * DHEAD + dcol];
        float o00 = (o[nf][0] * wu0 + wk0 * vs0.x) * iZ0;
        float o01 = (o[nf][1] * wu0 + wk0 * vs0.y) * iZ0;
        float o10 = (o[nf][2] * wu1 + wk1 * vs1.x) * iZ1;
        float o11 = (o[nf][3] * wu1 + wk1 * vs1.y) * iZ1;
        unsigned hw, lw;
        size_t u = (size_t)(h * DHEAD + dcol) >> 1;
        cvt_h2(o00, o01, hw, lw);
        g_ao2[(size_t)r0g * K2DIM + u] = make_uint2(hw, lw);
        cvt_h2(o10, o11, hw, lw);
        g_ao2[(size_t)r1g * K2DIM + u] = make_uint2(hw, lw);
    }
}

// ---------------- launch -------------------------------------------------------------
extern "C" void kernel_launch(void* const* d_in, const int* in_sizes, int n_in,
                              void* d_out, int out_size) {
    (void)in_sizes; (void)n_in; (void)out_size;
    const float* x        = (const float*)d_in[0];
    const float* pos_bias = (const float*)d_in[1];
    const float* gamma    = (const float*)d_in[2];
    const float* wq       = (const float*)d_in[3];
    const float* wk       = (const float*)d_in[4];
    const float* wv       = (const float*)d_in[5];
    const float* wo       = (const float*)d_in[6];
    float* out = (float*)d_out;

    uint2 *xn2_p, *wc2_p, *wo2_p, *ao2_p;
    cudaGetSymbolAddress((void**)&xn2_p, g_xn2);
    cudaGetSymbolAddress((void**)&wc2_p, g_wc2);
    cudaGetSymbolAddress((void**)&wo2_p, g_wo2);
    cudaGetSymbolAddress((void**)&ao2_p, g_ao2);

    const int GEMM_SMEM = 2 * 8192 * 4;      // 65536
    const int ATTN_SMEM = 33792 + 16896;     // 50688 (Kp4s + Vps)
    cudaFuncSetAttribute((const void*)gemm_h2_kernel<0, 1>, cudaFuncAttributeMaxDynamicSharedMemorySize, GEMM_SMEM);
    cudaFuncSetAttribute((const void*)gemm_h2_kernel<1, 3>, cudaFuncAttributeMaxDynamicSharedMemorySize, GEMM_SMEM);
    cudaFuncSetAttribute((const void*)attn_mma_kernel, cudaFuncAttributeMaxDynamicSharedMemorySize, ATTN_SMEM);

    dim3 tb(32, 8);
    transpose_split_all_kernel<<<8704, tb>>>(wq, wk, wv, wo, wc2_p, wo2_p);

    rmsnorm_split_kernel<<<SEQ, 256>>>(x, gamma);

    gemm_h2_kernel<1, 3><<<dim3(18, 16), 256, GEMM_SMEM>>>(xn2_p, wc2_p, nullptr, QKVN);

    vprep_kernel<<<256, 256>>>();
    vpart_kernel<<<16, 128>>>();
    vsuf_kernel<<<16, 128>>>();

    attn_mma_kernel<<<dim3(16, HEADS), 256, ATTN_SMEM>>>(pos_bias);

    gemm_h2_kernel<0, 1><<<dim3(16, 16), 256, GEMM_SMEM>>>(ao2_p, wo2_p, out, DIMM);
}